// round 1
// baseline (speedup 1.0000x reference)
#include <cuda_runtime.h>
#include <math.h>

#define BB 2
#define CC 256
#define NQ 4096

// ---------------- scratch (static device globals; no runtime alloc) ----------------
__device__ float g_Q  [BB*NQ*CC];          // LN'd query            [B,Nq,256]
__device__ float g_V0 [BB*4096*CC];        // value level0 pos-major [B,4096,256]
__device__ float g_V1 [BB*1024*CC];        // level1                 [B,1024,256]
__device__ float g_V2 [BB*256*CC];         // level2                 [B,256,256]
__device__ float g_OFF[BB*NQ*96];          // offsets                [B,Nq,96]
__device__ float g_WTS[BB*NQ*48];          // softmaxed weights      [B,Nq,48]
__device__ float g_ACC[(size_t)BB*NQ*1024];// sampled heads          [B,Nq,4*256]
__device__ float g_Y  [BB*NQ*CC];          // attn out proj          [B,Nq,256]
__device__ float g_Z  [BB*NQ*CC];          // post-LN residual       [B,Nq,256]
__device__ float g_H  [(size_t)BB*NQ*1024];// mlp hidden             [B,Nq,1024]

// ---------------- generic tiled SGEMM: C[m,n] = sum_k A(m,k)*W[n,k] (+bias)(+act)(+resid)
#define BM 64
#define BN 64
#define BK 16

__global__ void gemm_kernel(
    const float* __restrict__ A, long long sab, long long sam, long long sak,
    const float* __restrict__ W,               // [N,K] row-major
    const float* __restrict__ bias,            // [N] or null
    const float* __restrict__ R, long long srb, long long srm, long long srn,
    float* __restrict__ Cout, long long scb, long long scm, long long scn,
    int M, int N, int K, int act)
{
    __shared__ float As[BM][BK + 1];
    __shared__ float Ws[BN][BK + 1];

    const int tid = threadIdx.x;
    const int tx = tid & 15, ty = tid >> 4;
    const int m0 = blockIdx.y * BM, n0 = blockIdx.x * BN;

    A += (long long)blockIdx.z * sab;
    Cout += (long long)blockIdx.z * scb;
    if (R) R += (long long)blockIdx.z * srb;

    float acc[4][4] = {};

    for (int k0 = 0; k0 < K; k0 += BK) {
        if (sak == 1) {
            // A rows contiguous in K: coalesced along k
            #pragma unroll
            for (int i = 0; i < 4; i++) {
                int idx = tid + i * 256;
                int m = idx >> 4, k = idx & 15;
                int gm = m0 + m;
                As[m][k] = (gm < M) ? A[(long long)gm * sam + (k0 + k)] : 0.f;
            }
        } else {
            // A contiguous along M (sam==1 cases): coalesced along m
            #pragma unroll
            for (int i = 0; i < 4; i++) {
                int idx = tid + i * 256;
                int m = idx & 63, k = idx >> 6;
                int gm = m0 + m;
                As[m][k] = (gm < M) ? A[(long long)gm * sam + (long long)(k0 + k) * sak] : 0.f;
            }
        }
        #pragma unroll
        for (int i = 0; i < 4; i++) {
            int idx = tid + i * 256;
            int n = idx >> 4, k = idx & 15;
            int gn = n0 + n;
            Ws[n][k] = (gn < N) ? W[(long long)gn * K + k0 + k] : 0.f;
        }
        __syncthreads();

        #pragma unroll
        for (int k = 0; k < BK; k++) {
            float am[4], wn[4];
            #pragma unroll
            for (int i = 0; i < 4; i++) am[i] = As[ty * 4 + i][k];
            #pragma unroll
            for (int j = 0; j < 4; j++) wn[j] = Ws[tx * 4 + j][k];
            #pragma unroll
            for (int i = 0; i < 4; i++)
                #pragma unroll
                for (int j = 0; j < 4; j++)
                    acc[i][j] += am[i] * wn[j];
        }
        __syncthreads();
    }

    #pragma unroll
    for (int i = 0; i < 4; i++) {
        int gm = m0 + ty * 4 + i;
        if (gm >= M) continue;
        #pragma unroll
        for (int j = 0; j < 4; j++) {
            int gn = n0 + tx * 4 + j;
            if (gn >= N) continue;
            float v = acc[i][j];
            if (bias) v += bias[gn];
            if (act == 1) v = 0.5f * v * (1.f + erff(v * 0.70710678118654752f)); // exact gelu
            if (R) v += R[(long long)gm * srm + (long long)gn * srn];
            Cout[(long long)gm * scm + (long long)gn * scn] = v;
        }
    }
}

// ---------------- block reduction over 256 threads ----------------
__device__ __forceinline__ float block_sum256(float v)
{
    __shared__ float red[8];
    #pragma unroll
    for (int o = 16; o; o >>= 1) v += __shfl_xor_sync(0xffffffffu, v, o);
    __syncthreads();
    if ((threadIdx.x & 31) == 0) red[threadIdx.x >> 5] = v;
    __syncthreads();
    float s = red[0];
    #pragma unroll
    for (int i = 1; i < 8; i++) s += red[i];
    return s;
}

// LN in place on rows of [rows, 256]
__global__ void ln_kernel(float* __restrict__ X,
                          const float* __restrict__ g, const float* __restrict__ b)
{
    long long row = blockIdx.x;
    int c = threadIdx.x;
    float v = X[row * CC + c];
    float mu = block_sum256(v) * (1.f / CC);
    float d = v - mu;
    __syncthreads();
    float var = block_sum256(d * d) * (1.f / CC);
    float r = rsqrtf(var + 1e-5f);
    X[row * CC + c] = d * r * g[c] + b[c];
}

// Z = LN(S_seq + Y); S is [B,C,Hq,Wq] (strided), Y/Z are [rows,256]
__global__ void add_ln_kernel(const float* __restrict__ S, const float* __restrict__ Y,
                              float* __restrict__ Z,
                              const float* __restrict__ g, const float* __restrict__ b_)
{
    long long row = blockIdx.x;
    int c = threadIdx.x;
    int bb = (int)(row / NQ), nq = (int)(row % NQ);
    float v = S[((long long)bb * CC + c) * NQ + nq] + Y[row * CC + c];
    float mu = block_sum256(v) * (1.f / CC);
    float d = v - mu;
    __syncthreads();
    float var = block_sum256(d * d) * (1.f / CC);
    float r = rsqrtf(var + 1e-5f);
    Z[row * CC + c] = d * r * g[c] + b_[c];
}

// ---------------- temperature-scaled softmax over 12 pts per (b,q,h) ----------------
__global__ void softmax_kernel(float* __restrict__ WTS, const float* __restrict__ sim)
{
    int i = blockIdx.x * blockDim.x + threadIdx.x;
    if (i >= BB * NQ * 4) return;
    int h = i & 3;
    int q = i >> 2;                 // b*NQ + nq
    float s = sim[q] + 0.001f;      // TAU0 = 1
    float* w = WTS + (long long)q * 48 + h * 12;
    float v[12];
    float mx = -1e30f;
    #pragma unroll
    for (int t = 0; t < 12; t++) { v[t] = w[t] * s; mx = fmaxf(mx, v[t]); }
    float sum = 0.f;
    #pragma unroll
    for (int t = 0; t < 12; t++) { v[t] = expf(v[t] - mx); sum += v[t]; }
    float inv = 1.f / sum;
    #pragma unroll
    for (int t = 0; t < 12; t++) w[t] = v[t] * inv;
}

// ---------------- deformable bilinear sampling ----------------
// one block = one (b, nq, h); 64 threads x float4 = 256 channels
__global__ void sample_kernel(const float* __restrict__ OFF, const float* __restrict__ WTS,
                              const float* __restrict__ V0, const float* __restrict__ V1,
                              const float* __restrict__ V2, float* __restrict__ ACC)
{
    int gid = blockIdx.x;           // 0 .. BB*NQ*4-1
    int h = gid & 3;
    int q = gid >> 2;               // b*NQ + nq
    int bb = q / NQ, nq = q % NQ;
    int hq = nq >> 6, wq = nq & 63;

    __shared__ float sx[12], sy[12], sw[12];
    int t = threadIdx.x;
    if (t < 12) {
        float refx = (wq + 0.5f) * (1.f / 64.f);
        float refy = (hq + 0.5f) * (1.f / 64.f);
        const float* off = OFF + (long long)q * 96 + (h * 12 + t) * 2;
        sx[t] = tanhf(2.f * (refx + off[0]) - 1.f);
        sy[t] = tanhf(2.f * (refy + off[1]) - 1.f);
        sw[t] = WTS[(long long)q * 48 + h * 12 + t];
    }
    __syncthreads();

    float4 acc = make_float4(0.f, 0.f, 0.f, 0.f);
    int c4 = t * 4;

    #pragma unroll
    for (int l = 0; l < 3; l++) {
        int sz = 64 >> l;
        const float* Vb = (l == 0) ? V0 + (long long)bb * 4096 * CC
                        : (l == 1) ? V1 + (long long)bb * 1024 * CC
                                   : V2 + (long long)bb * 256 * CC;
        #pragma unroll
        for (int m = 0; m < 4; m++) {
            int p = l * 4 + m;
            float x = (sx[p] + 1.f) * 0.5f * (sz - 1);
            float y = (sy[p] + 1.f) * 0.5f * (sz - 1);
            float x0f = floorf(x), y0f = floorf(y);
            int x0 = (int)x0f, y0 = (int)y0f;
            float wx1 = x - x0f, wy1 = y - y0f;
            float wx0 = 1.f - wx1, wy0 = 1.f - wy1;
            float w = sw[p];
            #pragma unroll
            for (int dy = 0; dy < 2; dy++) {
                int yi = y0 + dy;
                if (yi < 0 || yi >= sz) continue;
                float wyv = dy ? wy1 : wy0;
                #pragma unroll
                for (int dx = 0; dx < 2; dx++) {
                    int xi = x0 + dx;
                    if (xi < 0 || xi >= sz) continue;
                    float tw = w * wyv * (dx ? wx1 : wx0);
                    const float4 v = __ldg((const float4*)(Vb + ((long long)(yi * sz + xi)) * CC + c4));
                    acc.x += tw * v.x; acc.y += tw * v.y;
                    acc.z += tw * v.z; acc.w += tw * v.w;
                }
            }
        }
    }
    float* out = ACC + (long long)q * 1024 + h * CC + c4;
    *(float4*)out = acc;
}

// ---------------- host orchestration ----------------
static void gemm(const float* A, long long sab, long long sam, long long sak,
                 const float* W, const float* bias,
                 const float* R, long long srb, long long srm, long long srn,
                 float* C, long long scb, long long scm, long long scn,
                 int M, int N, int K, int act, int batch)
{
    dim3 grid((N + BN - 1) / BN, (M + BM - 1) / BM, batch);
    gemm_kernel<<<grid, 256>>>(A, sab, sam, sak, W, bias, R, srb, srm, srn,
                               C, scb, scm, scn, M, N, K, act);
}

extern "C" void kernel_launch(void* const* d_in, const int* in_sizes, int n_in,
                              void* d_out, int out_size)
{
    const float* S     = (const float*)d_in[0];
    const float* f0    = (const float*)d_in[1];
    const float* f1    = (const float*)d_in[2];
    const float* f2    = (const float*)d_in[3];
    const float* sim   = (const float*)d_in[4];
    const float* vw0   = (const float*)d_in[5];
    const float* vb0   = (const float*)d_in[6];
    const float* vw1   = (const float*)d_in[7];
    const float* vb1   = (const float*)d_in[8];
    const float* vw2   = (const float*)d_in[9];
    const float* vb2   = (const float*)d_in[10];
    const float* q_w   = (const float*)d_in[11];
    const float* q_b   = (const float*)d_in[12];
    const float* off_w = (const float*)d_in[13];
    const float* off_b = (const float*)d_in[14];
    const float* wgt_w = (const float*)d_in[15];
    const float* wgt_b = (const float*)d_in[16];
    const float* out_w = (const float*)d_in[17];
    const float* out_b = (const float*)d_in[18];
    const float* lnq_g = (const float*)d_in[19];
    const float* lnq_b = (const float*)d_in[20];
    const float* lno_g = (const float*)d_in[21];
    const float* lno_b = (const float*)d_in[22];
    const float* fc1_w = (const float*)d_in[23];
    const float* fc1_b = (const float*)d_in[24];
    const float* fc2_w = (const float*)d_in[25];
    const float* fc2_b = (const float*)d_in[26];
    float* outp = (float*)d_out;

    float *Q, *V0, *V1, *V2, *OFF, *WTS, *ACC, *Y, *Z, *H;
    cudaGetSymbolAddress((void**)&Q,   g_Q);
    cudaGetSymbolAddress((void**)&V0,  g_V0);
    cudaGetSymbolAddress((void**)&V1,  g_V1);
    cudaGetSymbolAddress((void**)&V2,  g_V2);
    cudaGetSymbolAddress((void**)&OFF, g_OFF);
    cudaGetSymbolAddress((void**)&WTS, g_WTS);
    cudaGetSymbolAddress((void**)&ACC, g_ACC);
    cudaGetSymbolAddress((void**)&Y,   g_Y);
    cudaGetSymbolAddress((void**)&Z,   g_Z);
    cudaGetSymbolAddress((void**)&H,   g_H);

    // 1) Q = S_seq @ q_w^T + q_b  (A strided: S is [B,C,Nq] -> A(m=nq,k=c))
    gemm(S, (long long)CC * NQ, 1, NQ, q_w, q_b, nullptr, 0, 0, 0,
         Q, (long long)NQ * CC, CC, 1, NQ, CC, CC, 0, BB);
    // 2) LN(Q)
    ln_kernel<<<BB * NQ, 256>>>(Q, lnq_g, lnq_b);

    // 3) value projections, stored position-major [B, P, 256]
    gemm(f0, (long long)256 * 4096, 1, 4096, vw0, vb0, nullptr, 0, 0, 0,
         V0, (long long)4096 * CC, CC, 1, 4096, CC, 256, 0, BB);
    gemm(f1, (long long)512 * 1024, 1, 1024, vw1, vb1, nullptr, 0, 0, 0,
         V1, (long long)1024 * CC, CC, 1, 1024, CC, 512, 0, BB);
    gemm(f2, (long long)1024 * 256, 1, 256, vw2, vb2, nullptr, 0, 0, 0,
         V2, (long long)256 * CC, CC, 1, 256, CC, 1024, 0, BB);

    // 4) offsets + weights from Q (flattened rows = B*Nq)
    gemm(Q, 0, CC, 1, off_w, off_b, nullptr, 0, 0, 0,
         OFF, 0, 96, 1, BB * NQ, 96, CC, 0, 1);
    gemm(Q, 0, CC, 1, wgt_w, wgt_b, nullptr, 0, 0, 0,
         WTS, 0, 48, 1, BB * NQ, 48, CC, 0, 1);

    // 5) temperature softmax
    softmax_kernel<<<(BB * NQ * 4 + 255) / 256, 256>>>(WTS, sim);

    // 6) deformable sampling -> ACC [B*Nq, 1024]
    sample_kernel<<<BB * NQ * 4, 64>>>(OFF, WTS, V0, V1, V2, ACC);

    // 7) out projection: Y = ACC @ out_w^T + out_b
    gemm(ACC, 0, 1024, 1, out_w, out_b, nullptr, 0, 0, 0,
         Y, 0, CC, 1, BB * NQ, CC, 1024, 0, 1);

    // 8) Z = LN(S_seq + Y)
    add_ln_kernel<<<BB * NQ, 256>>>(S, Y, Z, lno_g, lno_b);

    // 9) H = gelu(Z @ fc1_w^T + fc1_b)
    gemm(Z, 0, CC, 1, fc1_w, fc1_b, nullptr, 0, 0, 0,
         H, 0, 1024, 1, BB * NQ, 1024, CC, 1, 1);

    // 10) out = Z + H @ fc2_w^T + fc2_b, written transposed into [B,C,Hq,Wq]
    gemm(H, (long long)NQ * 1024, 1024, 1, fc2_w, fc2_b,
         Z, (long long)NQ * CC, CC, 1,
         outp, (long long)CC * NQ, 1, NQ, NQ, CC, 1024, 0, BB);
}

// round 2
// speedup vs baseline: 1.7431x; 1.7431x over previous
#include <cuda_runtime.h>
#include <math.h>

#define BB 2
#define CC 256
#define NQ 4096

// ---------------- scratch (static device globals; no runtime alloc) ----------------
__device__ float g_Q  [BB*NQ*CC];
__device__ float g_V0 [BB*4096*CC];
__device__ float g_V1 [BB*1024*CC];
__device__ float g_V2 [BB*256*CC];
__device__ float g_OFF[BB*NQ*96];
__device__ float g_WTS[BB*NQ*48];
__device__ float g_ACC[(size_t)BB*NQ*1024];
__device__ float g_Y  [BB*NQ*CC];
__device__ float g_Z  [BB*NQ*CC];
__device__ float g_H  [(size_t)BB*NQ*1024];

// ---------------- double-buffered tiled SGEMM ----------------
// C[m,n] = sum_k A(m,k) * W[n,k] (+bias)(+gelu)(+resid), strided A / C.
// BM=128, BN=64, BK=16, 256 threads, 8x4 micro-tile per thread.
#define BM 128
#define BN 64
#define BK 16

__global__ void __launch_bounds__(256, 2) gemm_kernel(
    const float* __restrict__ A, long long sab, long long sam, long long sak,
    const float* __restrict__ W,               // [N,K] row-major
    const float* __restrict__ bias,            // [N] or null
    const float* __restrict__ R, long long srb, long long srm, long long srn,
    float* __restrict__ Cout, long long scb, long long scm, long long scn,
    int M, int N, int K, int act)
{
    __shared__ float As[2][BK][BM + 4];
    __shared__ float Ws[2][BK][BN + 4];

    const int tid = threadIdx.x;
    const int tx = tid & 15, ty = tid >> 4;
    const int m0 = blockIdx.y * BM, n0 = blockIdx.x * BN;
    const bool kc = (sak == 1);

    A    += (long long)blockIdx.z * sab;
    Cout += (long long)blockIdx.z * scb;
    if (R) R += (long long)blockIdx.z * srb;

    float4 rA0, rA1, rW;

#define LOAD_A(k0)                                                                        \
    if (kc) {                                                                             \
        rA0 = *(const float4*)(A + (long long)(m0 + (tid >> 2)) * sam + ((k0) + (tid & 3) * 4));          \
        rA1 = *(const float4*)(A + (long long)(m0 + ((tid + 256) >> 2)) * sam + ((k0) + (tid & 3) * 4));  \
    } else {                                                                              \
        rA0 = *(const float4*)(A + (long long)((k0) + (tid >> 5)) * sak + m0 + (tid & 31) * 4);           \
        rA1 = *(const float4*)(A + (long long)((k0) + ((tid + 256) >> 5)) * sak + m0 + (tid & 31) * 4);   \
    }

#define LOAD_W(k0)                                                                        \
    {   int gn_ = n0 + (tid >> 2);                                                        \
        rW = (gn_ < N) ? *(const float4*)(W + (long long)gn_ * K + (k0) + (tid & 3) * 4)  \
                       : make_float4(0.f, 0.f, 0.f, 0.f); }

#define STORE_AB(buf)                                                                     \
    if (kc) {                                                                             \
        int k4_ = (tid & 3) * 4;                                                          \
        int m_ = tid >> 2;                                                                \
        As[buf][k4_ + 0][m_] = rA0.x; As[buf][k4_ + 1][m_] = rA0.y;                       \
        As[buf][k4_ + 2][m_] = rA0.z; As[buf][k4_ + 3][m_] = rA0.w;                       \
        m_ = (tid + 256) >> 2;                                                            \
        As[buf][k4_ + 0][m_] = rA1.x; As[buf][k4_ + 1][m_] = rA1.y;                       \
        As[buf][k4_ + 2][m_] = rA1.z; As[buf][k4_ + 3][m_] = rA1.w;                       \
    } else {                                                                              \
        *(float4*)&As[buf][tid >> 5][(tid & 31) * 4] = rA0;                               \
        *(float4*)&As[buf][(tid + 256) >> 5][(tid & 31) * 4] = rA1;                       \
    }                                                                                     \
    {   int n_ = tid >> 2, k4_ = (tid & 3) * 4;                                           \
        Ws[buf][k4_ + 0][n_] = rW.x; Ws[buf][k4_ + 1][n_] = rW.y;                         \
        Ws[buf][k4_ + 2][n_] = rW.z; Ws[buf][k4_ + 3][n_] = rW.w; }

    LOAD_A(0); LOAD_W(0);
    STORE_AB(0);
    __syncthreads();

    float acc[8][4] = {};
    const int nk = K / BK;

    for (int t = 0; t < nk; t++) {
        const int buf = t & 1;
        const bool more = (t + 1 < nk);
        if (more) { LOAD_A((t + 1) * BK); LOAD_W((t + 1) * BK); }

        #pragma unroll
        for (int k = 0; k < BK; k++) {
            float4 a0 = *(const float4*)&As[buf][k][ty * 8];
            float4 a1 = *(const float4*)&As[buf][k][ty * 8 + 4];
            float4 b  = *(const float4*)&Ws[buf][k][tx * 4];
            float av[8] = {a0.x, a0.y, a0.z, a0.w, a1.x, a1.y, a1.z, a1.w};
            float bv[4] = {b.x, b.y, b.z, b.w};
            #pragma unroll
            for (int i = 0; i < 8; i++)
                #pragma unroll
                for (int j = 0; j < 4; j++)
                    acc[i][j] += av[i] * bv[j];
        }
        if (more) { STORE_AB(buf ^ 1); }
        __syncthreads();
    }

    // -------- epilogue --------
    float vals[8][4];
    #pragma unroll
    for (int j = 0; j < 4; j++) {
        int gn = n0 + tx * 4 + j;
        float bj = (bias && gn < N) ? bias[gn] : 0.f;
        #pragma unroll
        for (int i = 0; i < 8; i++) {
            float v = acc[i][j] + bj;
            if (act == 1) v = 0.5f * v * (1.f + erff(v * 0.70710678118654752f));
            vals[i][j] = v;
        }
    }
    if (R) {
        #pragma unroll
        for (int i = 0; i < 8; i++) {
            long long gm = m0 + ty * 8 + i;
            #pragma unroll
            for (int j = 0; j < 4; j++) {
                int gn = n0 + tx * 4 + j;
                if (gn < N) vals[i][j] += R[gm * srm + (long long)gn * srn];
            }
        }
    }

    int gn0 = n0 + tx * 4;
    if (scn == 1 && gn0 + 3 < N) {
        // row-contiguous store: float4 along n
        #pragma unroll
        for (int i = 0; i < 8; i++) {
            long long gm = m0 + ty * 8 + i;
            float4 v = make_float4(vals[i][0], vals[i][1], vals[i][2], vals[i][3]);
            *(float4*)(Cout + gm * scm + gn0) = v;
        }
    } else if (scm == 1) {
        // column-contiguous store: float4 along m (8 consecutive rows)
        #pragma unroll
        for (int j = 0; j < 4; j++) {
            int gn = gn0 + j;
            if (gn >= N) continue;
            float* base = Cout + (long long)gn * scn + (m0 + ty * 8);
            *(float4*)(base)     = make_float4(vals[0][j], vals[1][j], vals[2][j], vals[3][j]);
            *(float4*)(base + 4) = make_float4(vals[4][j], vals[5][j], vals[6][j], vals[7][j]);
        }
    } else {
        #pragma unroll
        for (int i = 0; i < 8; i++) {
            long long gm = m0 + ty * 8 + i;
            #pragma unroll
            for (int j = 0; j < 4; j++) {
                int gn = gn0 + j;
                if (gn < N) Cout[gm * scm + (long long)gn * scn] = vals[i][j];
            }
        }
    }
#undef LOAD_A
#undef LOAD_W
#undef STORE_AB
}

// ---------------- block reduction over 256 threads ----------------
__device__ __forceinline__ float block_sum256(float v)
{
    __shared__ float red[8];
    #pragma unroll
    for (int o = 16; o; o >>= 1) v += __shfl_xor_sync(0xffffffffu, v, o);
    __syncthreads();
    if ((threadIdx.x & 31) == 0) red[threadIdx.x >> 5] = v;
    __syncthreads();
    float s = red[0];
    #pragma unroll
    for (int i = 1; i < 8; i++) s += red[i];
    return s;
}

__global__ void ln_kernel(float* __restrict__ X,
                          const float* __restrict__ g, const float* __restrict__ b)
{
    long long row = blockIdx.x;
    int c = threadIdx.x;
    float v = X[row * CC + c];
    float mu = block_sum256(v) * (1.f / CC);
    float d = v - mu;
    __syncthreads();
    float var = block_sum256(d * d) * (1.f / CC);
    float r = rsqrtf(var + 1e-5f);
    X[row * CC + c] = d * r * g[c] + b[c];
}

__global__ void add_ln_kernel(const float* __restrict__ S, const float* __restrict__ Y,
                              float* __restrict__ Z,
                              const float* __restrict__ g, const float* __restrict__ b_)
{
    long long row = blockIdx.x;
    int c = threadIdx.x;
    int bb = (int)(row / NQ), nq = (int)(row % NQ);
    float v = S[((long long)bb * CC + c) * NQ + nq] + Y[row * CC + c];
    float mu = block_sum256(v) * (1.f / CC);
    float d = v - mu;
    __syncthreads();
    float var = block_sum256(d * d) * (1.f / CC);
    float r = rsqrtf(var + 1e-5f);
    Z[row * CC + c] = d * r * g[c] + b_[c];
}

__global__ void softmax_kernel(float* __restrict__ WTS, const float* __restrict__ sim)
{
    int i = blockIdx.x * blockDim.x + threadIdx.x;
    if (i >= BB * NQ * 4) return;
    int h = i & 3;
    int q = i >> 2;
    float s = sim[q] + 0.001f;
    float* w = WTS + (long long)q * 48 + h * 12;
    float v[12];
    float mx = -1e30f;
    #pragma unroll
    for (int t = 0; t < 12; t++) { v[t] = w[t] * s; mx = fmaxf(mx, v[t]); }
    float sum = 0.f;
    #pragma unroll
    for (int t = 0; t < 12; t++) { v[t] = expf(v[t] - mx); sum += v[t]; }
    float inv = 1.f / sum;
    #pragma unroll
    for (int t = 0; t < 12; t++) w[t] = v[t] * inv;
}

// ---------------- deformable bilinear sampling ----------------
__global__ void sample_kernel(const float* __restrict__ OFF, const float* __restrict__ WTS,
                              const float* __restrict__ V0, const float* __restrict__ V1,
                              const float* __restrict__ V2, float* __restrict__ ACC)
{
    int gid = blockIdx.x;
    int h = gid & 3;
    int q = gid >> 2;
    int bb = q / NQ, nq = q % NQ;
    int hq = nq >> 6, wq = nq & 63;

    __shared__ float sx[12], sy[12], sw[12];
    int t = threadIdx.x;
    if (t < 12) {
        float refx = (wq + 0.5f) * (1.f / 64.f);
        float refy = (hq + 0.5f) * (1.f / 64.f);
        const float* off = OFF + (long long)q * 96 + (h * 12 + t) * 2;
        sx[t] = tanhf(2.f * (refx + off[0]) - 1.f);
        sy[t] = tanhf(2.f * (refy + off[1]) - 1.f);
        sw[t] = WTS[(long long)q * 48 + h * 12 + t];
    }
    __syncthreads();

    float4 acc = make_float4(0.f, 0.f, 0.f, 0.f);
    int c4 = t * 4;

    #pragma unroll
    for (int l = 0; l < 3; l++) {
        int sz = 64 >> l;
        const float* Vb = (l == 0) ? V0 + (long long)bb * 4096 * CC
                        : (l == 1) ? V1 + (long long)bb * 1024 * CC
                                   : V2 + (long long)bb * 256 * CC;
        #pragma unroll
        for (int m = 0; m < 4; m++) {
            int p = l * 4 + m;
            float x = (sx[p] + 1.f) * 0.5f * (sz - 1);
            float y = (sy[p] + 1.f) * 0.5f * (sz - 1);
            float x0f = floorf(x), y0f = floorf(y);
            int x0 = (int)x0f, y0 = (int)y0f;
            float wx1 = x - x0f, wy1 = y - y0f;
            float wx0 = 1.f - wx1, wy0 = 1.f - wy1;
            float w = sw[p];
            #pragma unroll
            for (int dy = 0; dy < 2; dy++) {
                int yi = y0 + dy;
                if (yi < 0 || yi >= sz) continue;
                float wyv = dy ? wy1 : wy0;
                #pragma unroll
                for (int dx = 0; dx < 2; dx++) {
                    int xi = x0 + dx;
                    if (xi < 0 || xi >= sz) continue;
                    float tw = w * wyv * (dx ? wx1 : wx0);
                    const float4 v = __ldg((const float4*)(Vb + ((long long)(yi * sz + xi)) * CC + c4));
                    acc.x += tw * v.x; acc.y += tw * v.y;
                    acc.z += tw * v.z; acc.w += tw * v.w;
                }
            }
        }
    }
    float* out = ACC + (long long)q * 1024 + h * CC + c4;
    *(float4*)out = acc;
}

// ---------------- host orchestration ----------------
static void gemm(const float* A, long long sab, long long sam, long long sak,
                 const float* W, const float* bias,
                 const float* R, long long srb, long long srm, long long srn,
                 float* C, long long scb, long long scm, long long scn,
                 int M, int N, int K, int act, int batch)
{
    dim3 grid((N + BN - 1) / BN, (M + BM - 1) / BM, batch);
    gemm_kernel<<<grid, 256>>>(A, sab, sam, sak, W, bias, R, srb, srm, srn,
                               C, scb, scm, scn, M, N, K, act);
}

extern "C" void kernel_launch(void* const* d_in, const int* in_sizes, int n_in,
                              void* d_out, int out_size)
{
    const float* S     = (const float*)d_in[0];
    const float* f0    = (const float*)d_in[1];
    const float* f1    = (const float*)d_in[2];
    const float* f2    = (const float*)d_in[3];
    const float* sim   = (const float*)d_in[4];
    const float* vw0   = (const float*)d_in[5];
    const float* vb0   = (const float*)d_in[6];
    const float* vw1   = (const float*)d_in[7];
    const float* vb1   = (const float*)d_in[8];
    const float* vw2   = (const float*)d_in[9];
    const float* vb2   = (const float*)d_in[10];
    const float* q_w   = (const float*)d_in[11];
    const float* q_b   = (const float*)d_in[12];
    const float* off_w = (const float*)d_in[13];
    const float* off_b = (const float*)d_in[14];
    const float* wgt_w = (const float*)d_in[15];
    const float* wgt_b = (const float*)d_in[16];
    const float* out_w = (const float*)d_in[17];
    const float* out_b = (const float*)d_in[18];
    const float* lnq_g = (const float*)d_in[19];
    const float* lnq_b = (const float*)d_in[20];
    const float* lno_g = (const float*)d_in[21];
    const float* lno_b = (const float*)d_in[22];
    const float* fc1_w = (const float*)d_in[23];
    const float* fc1_b = (const float*)d_in[24];
    const float* fc2_w = (const float*)d_in[25];
    const float* fc2_b = (const float*)d_in[26];
    float* outp = (float*)d_out;

    float *Q, *V0, *V1, *V2, *OFF, *WTS, *ACC, *Y, *Z, *H;
    cudaGetSymbolAddress((void**)&Q,   g_Q);
    cudaGetSymbolAddress((void**)&V0,  g_V0);
    cudaGetSymbolAddress((void**)&V1,  g_V1);
    cudaGetSymbolAddress((void**)&V2,  g_V2);
    cudaGetSymbolAddress((void**)&OFF, g_OFF);
    cudaGetSymbolAddress((void**)&WTS, g_WTS);
    cudaGetSymbolAddress((void**)&ACC, g_ACC);
    cudaGetSymbolAddress((void**)&Y,   g_Y);
    cudaGetSymbolAddress((void**)&Z,   g_Z);
    cudaGetSymbolAddress((void**)&H,   g_H);

    // 1) Q = S_seq @ q_w^T + q_b  (A contiguous along m: sam=1, sak=NQ)
    gemm(S, (long long)CC * NQ, 1, NQ, q_w, q_b, nullptr, 0, 0, 0,
         Q, (long long)NQ * CC, CC, 1, NQ, CC, CC, 0, BB);
    ln_kernel<<<BB * NQ, 256>>>(Q, lnq_g, lnq_b);

    // 3) value projections -> position-major [B,P,256]
    gemm(f0, (long long)256 * 4096, 1, 4096, vw0, vb0, nullptr, 0, 0, 0,
         V0, (long long)4096 * CC, CC, 1, 4096, CC, 256, 0, BB);
    gemm(f1, (long long)512 * 1024, 1, 1024, vw1, vb1, nullptr, 0, 0, 0,
         V1, (long long)1024 * CC, CC, 1, 1024, CC, 512, 0, BB);
    gemm(f2, (long long)1024 * 256, 1, 256, vw2, vb2, nullptr, 0, 0, 0,
         V2, (long long)256 * CC, CC, 1, 256, CC, 1024, 0, BB);

    // 4) offsets + weights
    gemm(Q, 0, CC, 1, off_w, off_b, nullptr, 0, 0, 0,
         OFF, 0, 96, 1, BB * NQ, 96, CC, 0, 1);
    gemm(Q, 0, CC, 1, wgt_w, wgt_b, nullptr, 0, 0, 0,
         WTS, 0, 48, 1, BB * NQ, 48, CC, 0, 1);

    // 5) temperature softmax
    softmax_kernel<<<(BB * NQ * 4 + 255) / 256, 256>>>(WTS, sim);

    // 6) deformable sampling
    sample_kernel<<<BB * NQ * 4, 64>>>(OFF, WTS, V0, V1, V2, ACC);

    // 7) Y = ACC @ out_w^T + out_b
    gemm(ACC, 0, 1024, 1, out_w, out_b, nullptr, 0, 0, 0,
         Y, 0, CC, 1, BB * NQ, CC, 1024, 0, 1);

    // 8) Z = LN(S_seq + Y)
    add_ln_kernel<<<BB * NQ, 256>>>(S, Y, Z, lno_g, lno_b);

    // 9) H = gelu(Z @ fc1_w^T + fc1_b)
    gemm(Z, 0, CC, 1, fc1_w, fc1_b, nullptr, 0, 0, 0,
         H, 0, 1024, 1, BB * NQ, 1024, CC, 1, 1);

    // 10) out = Z + H @ fc2_w^T + fc2_b, transposed store into [B,C,Hq,Wq]
    gemm(H, (long long)NQ * 1024, 1024, 1, fc2_w, fc2_b,
         Z, (long long)NQ * CC, CC, 1,
         outp, (long long)CC * NQ, 1, NQ, NQ, CC, 1024, 0, BB);
}

// round 3
// speedup vs baseline: 2.5245x; 1.4483x over previous
#include <cuda_runtime.h>
#include <math.h>

#define BB 2
#define CC 256
#define NQ 4096

// ---------------- scratch ----------------
__device__ float g_Q  [BB*NQ*CC];
__device__ float g_V0 [BB*4096*CC];
__device__ float g_V1 [BB*1024*CC];
__device__ float g_V2 [BB*256*CC];
__device__ float g_OFF[BB*NQ*96];
__device__ float g_WTS[BB*NQ*48];
__device__ float g_ACC[(size_t)BB*NQ*1024];
__device__ float g_Y  [BB*NQ*CC];
__device__ float g_Z  [BB*NQ*CC];
__device__ float g_H  [(size_t)BB*NQ*1024];

#define BM 128
#define BN 64

// ---------------- tf32 helpers ----------------
__device__ __forceinline__ float tf32_rna(float x)
{
    unsigned r;
    asm("cvt.rna.tf32.f32 %0, %1;" : "=r"(r) : "f"(x));
    return __uint_as_float(r);
}

__device__ __forceinline__ void mma8(float d[4],
                                     unsigned a0, unsigned a1, unsigned a2, unsigned a3,
                                     unsigned b0, unsigned b1)
{
    asm volatile(
        "mma.sync.aligned.m16n8k8.row.col.f32.tf32.tf32.f32 "
        "{%0,%1,%2,%3},{%4,%5,%6,%7},{%8,%9},{%0,%1,%2,%3};"
        : "+f"(d[0]), "+f"(d[1]), "+f"(d[2]), "+f"(d[3])
        : "r"(a0), "r"(a1), "r"(a2), "r"(a3), "r"(b0), "r"(b1));
}

__device__ __forceinline__ float gelu_exact(float v)
{
    return 0.5f * v * (1.f + erff(v * 0.70710678118654752f));
}

#define U32(x) __float_as_uint(x)

// =====================================================================
// gemm_tc: tf32 tensor-core GEMM.  C[m,n] = sum_k A(m,k)*W[n,k]
// BM=128 BN=64 BK=16, 256 thr, warp grid 2(m) x 4(n), warp tile 64x16.
// All dims must be multiples of the tile (guaranteed by call sites).
// =====================================================================
__global__ void __launch_bounds__(256, 2) gemm_tc(
    const float* __restrict__ A, long long sab, long long sam, long long sak,
    const float* __restrict__ W,
    const float* __restrict__ bias,
    const float* __restrict__ R, long long srb, long long srm, long long srn,
    float* __restrict__ Cout, long long scb, long long scm, long long scn,
    int M, int N, int K, int act)
{
    __shared__ float Ah[2][16][BM + 8];
    __shared__ float Bs[2][16][BN + 8];

    const int tid = threadIdx.x;
    const int lane = tid & 31, warp = tid >> 5;
    const int g = lane >> 2, tg = lane & 3;
    const int wm = (warp >> 2) * 64, wn = (warp & 3) * 16;
    const int m0 = blockIdx.y * BM, n0 = blockIdx.x * BN;
    const bool kc = (sak == 1);

    A    += (long long)blockIdx.z * sab;
    Cout += (long long)blockIdx.z * scb;
    if (R) R += (long long)blockIdx.z * srb;

    float4 rA0, rA1, rW;

#define LOAD(k0)                                                                           \
    if (kc) {                                                                              \
        rA0 = *(const float4*)(A + (long long)(m0 + (tid >> 2)) * sam + ((k0) + (tid & 3) * 4));         \
        rA1 = *(const float4*)(A + (long long)(m0 + 64 + (tid >> 2)) * sam + ((k0) + (tid & 3) * 4));    \
    } else {                                                                               \
        rA0 = *(const float4*)(A + (long long)((k0) + (tid >> 5)) * sak + m0 + (tid & 31) * 4);          \
        rA1 = *(const float4*)(A + (long long)((k0) + 8 + (tid >> 5)) * sak + m0 + (tid & 31) * 4);      \
    }                                                                                      \
    rW = *(const float4*)(W + (long long)(n0 + (tid >> 2)) * K + (k0) + (tid & 3) * 4);

#define STORE(buf)                                                                         \
    if (kc) {                                                                              \
        int k4_ = (tid & 3) * 4, m_ = tid >> 2;                                            \
        Ah[buf][k4_ + 0][m_]      = tf32_rna(rA0.x);                                       \
        Ah[buf][k4_ + 1][m_]      = tf32_rna(rA0.y);                                       \
        Ah[buf][k4_ + 2][m_]      = tf32_rna(rA0.z);                                       \
        Ah[buf][k4_ + 3][m_]      = tf32_rna(rA0.w);                                       \
        Ah[buf][k4_ + 0][m_ + 64] = tf32_rna(rA1.x);                                       \
        Ah[buf][k4_ + 1][m_ + 64] = tf32_rna(rA1.y);                                       \
        Ah[buf][k4_ + 2][m_ + 64] = tf32_rna(rA1.z);                                       \
        Ah[buf][k4_ + 3][m_ + 64] = tf32_rna(rA1.w);                                       \
    } else {                                                                               \
        float4 c0 = make_float4(tf32_rna(rA0.x), tf32_rna(rA0.y), tf32_rna(rA0.z), tf32_rna(rA0.w));     \
        float4 c1 = make_float4(tf32_rna(rA1.x), tf32_rna(rA1.y), tf32_rna(rA1.z), tf32_rna(rA1.w));     \
        *(float4*)&Ah[buf][tid >> 5][(tid & 31) * 4]     = c0;                             \
        *(float4*)&Ah[buf][8 + (tid >> 5)][(tid & 31) * 4] = c1;                           \
    }                                                                                      \
    {   int n_ = tid >> 2, k4_ = (tid & 3) * 4;                                            \
        Bs[buf][k4_ + 0][n_] = tf32_rna(rW.x);                                             \
        Bs[buf][k4_ + 1][n_] = tf32_rna(rW.y);                                             \
        Bs[buf][k4_ + 2][n_] = tf32_rna(rW.z);                                             \
        Bs[buf][k4_ + 3][n_] = tf32_rna(rW.w); }

    LOAD(0); STORE(0);
    __syncthreads();

    float acc[4][2][4] = {};
    const int nk = K / 16;

    for (int t = 0; t < nk; t++) {
        const int buf = t & 1;
        const bool more = (t + 1 < nk);
        if (more) { LOAD((t + 1) * 16); }

        #pragma unroll
        for (int kk = 0; kk < 16; kk += 8) {
            unsigned bfr[2][2];
            #pragma unroll
            for (int nt = 0; nt < 2; nt++) {
                bfr[nt][0] = U32(Bs[buf][kk + tg][wn + 8 * nt + g]);
                bfr[nt][1] = U32(Bs[buf][kk + tg + 4][wn + 8 * nt + g]);
            }
            #pragma unroll
            for (int mt = 0; mt < 4; mt++) {
                unsigned a0 = U32(Ah[buf][kk + tg][wm + 16 * mt + g]);
                unsigned a1 = U32(Ah[buf][kk + tg][wm + 16 * mt + g + 8]);
                unsigned a2 = U32(Ah[buf][kk + tg + 4][wm + 16 * mt + g]);
                unsigned a3 = U32(Ah[buf][kk + tg + 4][wm + 16 * mt + g + 8]);
                #pragma unroll
                for (int nt = 0; nt < 2; nt++)
                    mma8(acc[mt][nt], a0, a1, a2, a3, bfr[nt][0], bfr[nt][1]);
            }
        }
        if (more) { STORE(buf ^ 1); }
        __syncthreads();
    }
#undef LOAD
#undef STORE

    // epilogue
    #pragma unroll
    for (int mt = 0; mt < 4; mt++) {
        int gm0 = m0 + wm + 16 * mt + g;
        #pragma unroll
        for (int nt = 0; nt < 2; nt++) {
            int gn0 = n0 + wn + 8 * nt + 2 * tg;
            float v0 = acc[mt][nt][0], v1 = acc[mt][nt][1];
            float v2 = acc[mt][nt][2], v3 = acc[mt][nt][3];
            if (bias) {
                float b0 = bias[gn0], b1 = bias[gn0 + 1];
                v0 += b0; v1 += b1; v2 += b0; v3 += b1;
            }
            if (act) {
                v0 = gelu_exact(v0); v1 = gelu_exact(v1);
                v2 = gelu_exact(v2); v3 = gelu_exact(v3);
            }
            if (R) {
                v0 += R[(long long)gm0 * srm + (long long)gn0 * srn];
                v1 += R[(long long)gm0 * srm + (long long)(gn0 + 1) * srn];
                v2 += R[(long long)(gm0 + 8) * srm + (long long)gn0 * srn];
                v3 += R[(long long)(gm0 + 8) * srm + (long long)(gn0 + 1) * srn];
            }
            if (scn == 1) {
                *(float2*)(Cout + (long long)gm0 * scm + gn0)       = make_float2(v0, v1);
                *(float2*)(Cout + (long long)(gm0 + 8) * scm + gn0) = make_float2(v2, v3);
            } else {
                Cout[(long long)gm0 * scm + (long long)gn0 * scn]             = v0;
                Cout[(long long)gm0 * scm + (long long)(gn0 + 1) * scn]       = v1;
                Cout[(long long)(gm0 + 8) * scm + (long long)gn0 * scn]       = v2;
                Cout[(long long)(gm0 + 8) * scm + (long long)(gn0 + 1) * scn] = v3;
            }
        }
    }
}

// =====================================================================
// gemm_tc3: 3xTF32 (fp32-accurate) GEMM for the offset-sensitive path.
// BK=8, hi/lo split, 3 MMAs per tile. bias only, scn==1 stores, N guarded.
// =====================================================================
__global__ void __launch_bounds__(256, 2) gemm_tc3(
    const float* __restrict__ A, long long sab, long long sam, long long sak,
    const float* __restrict__ W,
    const float* __restrict__ bias,
    float* __restrict__ Cout, long long scb, long long scm,
    int M, int N, int K)
{
    __shared__ float Ah[2][8][BM + 8];
    __shared__ float Al[2][8][BM + 8];
    __shared__ float Bh[2][8][BN + 8];
    __shared__ float Bl[2][8][BN + 8];

    const int tid = threadIdx.x;
    const int lane = tid & 31, warp = tid >> 5;
    const int g = lane >> 2, tg = lane & 3;
    const int wm = (warp >> 2) * 64, wn = (warp & 3) * 16;
    const int m0 = blockIdx.y * BM, n0 = blockIdx.x * BN;
    const bool kc = (sak == 1);

    A    += (long long)blockIdx.z * sab;
    Cout += (long long)blockIdx.z * scb;

    float4 rA, rW;

#define LOAD3(k0)                                                                          \
    if (kc) {                                                                              \
        rA = *(const float4*)(A + (long long)(m0 + (tid >> 1)) * sam + ((k0) + (tid & 1) * 4));          \
    } else {                                                                               \
        rA = *(const float4*)(A + (long long)((k0) + (tid >> 5)) * sak + m0 + (tid & 31) * 4);           \
    }                                                                                      \
    if (tid < 128) {                                                                       \
        int gn_ = n0 + (tid >> 1);                                                         \
        rW = (gn_ < N) ? *(const float4*)(W + (long long)gn_ * K + (k0) + (tid & 1) * 4)   \
                       : make_float4(0.f, 0.f, 0.f, 0.f);                                  \
    }

#define SPLIT(x, hi, lo) { hi = tf32_rna(x); lo = tf32_rna((x) - hi); }

#define STORE3(buf)                                                                        \
    {   float h_, l_;                                                                      \
        if (kc) {                                                                          \
            int k4_ = (tid & 1) * 4, m_ = tid >> 1;                                        \
            SPLIT(rA.x, h_, l_); Ah[buf][k4_ + 0][m_] = h_; Al[buf][k4_ + 0][m_] = l_;     \
            SPLIT(rA.y, h_, l_); Ah[buf][k4_ + 1][m_] = h_; Al[buf][k4_ + 1][m_] = l_;     \
            SPLIT(rA.z, h_, l_); Ah[buf][k4_ + 2][m_] = h_; Al[buf][k4_ + 2][m_] = l_;     \
            SPLIT(rA.w, h_, l_); Ah[buf][k4_ + 3][m_] = h_; Al[buf][k4_ + 3][m_] = l_;     \
        } else {                                                                           \
            int row_ = tid >> 5, col_ = (tid & 31) * 4;                                    \
            SPLIT(rA.x, h_, l_); Ah[buf][row_][col_ + 0] = h_; Al[buf][row_][col_ + 0] = l_;  \
            SPLIT(rA.y, h_, l_); Ah[buf][row_][col_ + 1] = h_; Al[buf][row_][col_ + 1] = l_;  \
            SPLIT(rA.z, h_, l_); Ah[buf][row_][col_ + 2] = h_; Al[buf][row_][col_ + 2] = l_;  \
            SPLIT(rA.w, h_, l_); Ah[buf][row_][col_ + 3] = h_; Al[buf][row_][col_ + 3] = l_;  \
        }                                                                                  \
        if (tid < 128) {                                                                   \
            int n_ = tid >> 1, k4_ = (tid & 1) * 4;                                        \
            SPLIT(rW.x, h_, l_); Bh[buf][k4_ + 0][n_] = h_; Bl[buf][k4_ + 0][n_] = l_;     \
            SPLIT(rW.y, h_, l_); Bh[buf][k4_ + 1][n_] = h_; Bl[buf][k4_ + 1][n_] = l_;     \
            SPLIT(rW.z, h_, l_); Bh[buf][k4_ + 2][n_] = h_; Bl[buf][k4_ + 2][n_] = l_;     \
            SPLIT(rW.w, h_, l_); Bh[buf][k4_ + 3][n_] = h_; Bl[buf][k4_ + 3][n_] = l_;     \
        }                                                                                  \
    }

    LOAD3(0); STORE3(0);
    __syncthreads();

    float acc[4][2][4] = {};
    const int nk = K / 8;

    for (int t = 0; t < nk; t++) {
        const int buf = t & 1;
        const bool more = (t + 1 < nk);
        if (more) { LOAD3((t + 1) * 8); }

        unsigned bh[2][2], bl[2][2];
        #pragma unroll
        for (int nt = 0; nt < 2; nt++) {
            bh[nt][0] = U32(Bh[buf][tg][wn + 8 * nt + g]);
            bh[nt][1] = U32(Bh[buf][tg + 4][wn + 8 * nt + g]);
            bl[nt][0] = U32(Bl[buf][tg][wn + 8 * nt + g]);
            bl[nt][1] = U32(Bl[buf][tg + 4][wn + 8 * nt + g]);
        }
        #pragma unroll
        for (int mt = 0; mt < 4; mt++) {
            unsigned a0 = U32(Ah[buf][tg][wm + 16 * mt + g]);
            unsigned a1 = U32(Ah[buf][tg][wm + 16 * mt + g + 8]);
            unsigned a2 = U32(Ah[buf][tg + 4][wm + 16 * mt + g]);
            unsigned a3 = U32(Ah[buf][tg + 4][wm + 16 * mt + g + 8]);
            unsigned l0 = U32(Al[buf][tg][wm + 16 * mt + g]);
            unsigned l1 = U32(Al[buf][tg][wm + 16 * mt + g + 8]);
            unsigned l2 = U32(Al[buf][tg + 4][wm + 16 * mt + g]);
            unsigned l3 = U32(Al[buf][tg + 4][wm + 16 * mt + g + 8]);
            #pragma unroll
            for (int nt = 0; nt < 2; nt++) {
                mma8(acc[mt][nt], l0, l1, l2, l3, bh[nt][0], bh[nt][1]);  // lo*hi
                mma8(acc[mt][nt], a0, a1, a2, a3, bl[nt][0], bl[nt][1]);  // hi*lo
                mma8(acc[mt][nt], a0, a1, a2, a3, bh[nt][0], bh[nt][1]);  // hi*hi
            }
        }
        if (more) { STORE3(buf ^ 1); }
        __syncthreads();
    }
#undef LOAD3
#undef STORE3
#undef SPLIT

    #pragma unroll
    for (int mt = 0; mt < 4; mt++) {
        int gm0 = m0 + wm + 16 * mt + g;
        #pragma unroll
        for (int nt = 0; nt < 2; nt++) {
            int gn0 = n0 + wn + 8 * nt + 2 * tg;
            if (gn0 >= N) continue;
            float v0 = acc[mt][nt][0], v1 = acc[mt][nt][1];
            float v2 = acc[mt][nt][2], v3 = acc[mt][nt][3];
            if (bias) {
                float b0 = bias[gn0], b1 = bias[gn0 + 1];
                v0 += b0; v1 += b1; v2 += b0; v3 += b1;
            }
            *(float2*)(Cout + (long long)gm0 * scm + gn0)       = make_float2(v0, v1);
            *(float2*)(Cout + (long long)(gm0 + 8) * scm + gn0) = make_float2(v2, v3);
        }
    }
}

// ---------------- block reduction ----------------
__device__ __forceinline__ float block_sum256(float v)
{
    __shared__ float red[8];
    #pragma unroll
    for (int o = 16; o; o >>= 1) v += __shfl_xor_sync(0xffffffffu, v, o);
    __syncthreads();
    if ((threadIdx.x & 31) == 0) red[threadIdx.x >> 5] = v;
    __syncthreads();
    float s = red[0];
    #pragma unroll
    for (int i = 1; i < 8; i++) s += red[i];
    return s;
}

__global__ void ln_kernel(float* __restrict__ X,
                          const float* __restrict__ g, const float* __restrict__ b)
{
    long long row = blockIdx.x;
    int c = threadIdx.x;
    float v = X[row * CC + c];
    float mu = block_sum256(v) * (1.f / CC);
    float d = v - mu;
    __syncthreads();
    float var = block_sum256(d * d) * (1.f / CC);
    float r = rsqrtf(var + 1e-5f);
    X[row * CC + c] = d * r * g[c] + b[c];
}

__global__ void add_ln_kernel(const float* __restrict__ S, const float* __restrict__ Y,
                              float* __restrict__ Z,
                              const float* __restrict__ g, const float* __restrict__ b_)
{
    long long row = blockIdx.x;
    int c = threadIdx.x;
    int bb = (int)(row / NQ), nq = (int)(row % NQ);
    float v = S[((long long)bb * CC + c) * NQ + nq] + Y[row * CC + c];
    float mu = block_sum256(v) * (1.f / CC);
    float d = v - mu;
    __syncthreads();
    float var = block_sum256(d * d) * (1.f / CC);
    float r = rsqrtf(var + 1e-5f);
    Z[row * CC + c] = d * r * g[c] + b_[c];
}

__global__ void softmax_kernel(float* __restrict__ WTS, const float* __restrict__ sim)
{
    int i = blockIdx.x * blockDim.x + threadIdx.x;
    if (i >= BB * NQ * 4) return;
    int h = i & 3;
    int q = i >> 2;
    float s = sim[q] + 0.001f;
    float* w = WTS + (long long)q * 48 + h * 12;
    float v[12];
    float mx = -1e30f;
    #pragma unroll
    for (int t = 0; t < 12; t++) { v[t] = w[t] * s; mx = fmaxf(mx, v[t]); }
    float sum = 0.f;
    #pragma unroll
    for (int t = 0; t < 12; t++) { v[t] = expf(v[t] - mx); sum += v[t]; }
    float inv = 1.f / sum;
    #pragma unroll
    for (int t = 0; t < 12; t++) w[t] = v[t] * inv;
}

// ---------------- deformable bilinear sampling ----------------
__global__ void sample_kernel(const float* __restrict__ OFF, const float* __restrict__ WTS,
                              const float* __restrict__ V0, const float* __restrict__ V1,
                              const float* __restrict__ V2, float* __restrict__ ACC)
{
    int gid = blockIdx.x;
    int h = gid & 3;
    int q = gid >> 2;
    int bb = q / NQ, nq = q % NQ;
    int hq = nq >> 6, wq = nq & 63;

    __shared__ float sx[12], sy[12], sw[12];
    int t = threadIdx.x;
    if (t < 12) {
        float refx = (wq + 0.5f) * (1.f / 64.f);
        float refy = (hq + 0.5f) * (1.f / 64.f);
        const float* off = OFF + (long long)q * 96 + (h * 12 + t) * 2;
        sx[t] = tanhf(2.f * (refx + off[0]) - 1.f);
        sy[t] = tanhf(2.f * (refy + off[1]) - 1.f);
        sw[t] = WTS[(long long)q * 48 + h * 12 + t];
    }
    __syncthreads();

    float4 acc = make_float4(0.f, 0.f, 0.f, 0.f);
    int c4 = t * 4;

    #pragma unroll
    for (int l = 0; l < 3; l++) {
        int sz = 64 >> l;
        const float* Vb = (l == 0) ? V0 + (long long)bb * 4096 * CC
                        : (l == 1) ? V1 + (long long)bb * 1024 * CC
                                   : V2 + (long long)bb * 256 * CC;
        #pragma unroll
        for (int m = 0; m < 4; m++) {
            int p = l * 4 + m;
            float x = (sx[p] + 1.f) * 0.5f * (sz - 1);
            float y = (sy[p] + 1.f) * 0.5f * (sz - 1);
            float x0f = floorf(x), y0f = floorf(y);
            int x0 = (int)x0f, y0 = (int)y0f;
            float wx1 = x - x0f, wy1 = y - y0f;
            float wx0 = 1.f - wx1, wy0 = 1.f - wy1;
            float w = sw[p];
            #pragma unroll
            for (int dy = 0; dy < 2; dy++) {
                int yi = y0 + dy;
                if (yi < 0 || yi >= sz) continue;
                float wyv = dy ? wy1 : wy0;
                #pragma unroll
                for (int dx = 0; dx < 2; dx++) {
                    int xi = x0 + dx;
                    if (xi < 0 || xi >= sz) continue;
                    float tw = w * wyv * (dx ? wx1 : wx0);
                    const float4 v = __ldg((const float4*)(Vb + ((long long)(yi * sz + xi)) * CC + c4));
                    acc.x += tw * v.x; acc.y += tw * v.y;
                    acc.z += tw * v.z; acc.w += tw * v.w;
                }
            }
        }
    }
    float* out = ACC + (long long)q * 1024 + h * CC + c4;
    *(float4*)out = acc;
}

// ---------------- host orchestration ----------------
static void gemm_fast(const float* A, long long sab, long long sam, long long sak,
                      const float* W, const float* bias,
                      const float* R, long long srb, long long srm, long long srn,
                      float* C, long long scb, long long scm, long long scn,
                      int M, int N, int K, int act, int batch)
{
    dim3 grid(N / BN, M / BM, batch);
    gemm_tc<<<grid, 256>>>(A, sab, sam, sak, W, bias, R, srb, srm, srn,
                           C, scb, scm, scn, M, N, K, act);
}

static void gemm_prec(const float* A, long long sab, long long sam, long long sak,
                      const float* W, const float* bias,
                      float* C, long long scb, long long scm,
                      int M, int N, int K, int batch)
{
    dim3 grid((N + BN - 1) / BN, M / BM, batch);
    gemm_tc3<<<grid, 256>>>(A, sab, sam, sak, W, bias, C, scb, scm, M, N, K);
}

extern "C" void kernel_launch(void* const* d_in, const int* in_sizes, int n_in,
                              void* d_out, int out_size)
{
    const float* S     = (const float*)d_in[0];
    const float* f0    = (const float*)d_in[1];
    const float* f1    = (const float*)d_in[2];
    const float* f2    = (const float*)d_in[3];
    const float* sim   = (const float*)d_in[4];
    const float* vw0   = (const float*)d_in[5];
    const float* vb0   = (const float*)d_in[6];
    const float* vw1   = (const float*)d_in[7];
    const float* vb1   = (const float*)d_in[8];
    const float* vw2   = (const float*)d_in[9];
    const float* vb2   = (const float*)d_in[10];
    const float* q_w   = (const float*)d_in[11];
    const float* q_b   = (const float*)d_in[12];
    const float* off_w = (const float*)d_in[13];
    const float* off_b = (const float*)d_in[14];
    const float* wgt_w = (const float*)d_in[15];
    const float* wgt_b = (const float*)d_in[16];
    const float* out_w = (const float*)d_in[17];
    const float* out_b = (const float*)d_in[18];
    const float* lnq_g = (const float*)d_in[19];
    const float* lnq_b = (const float*)d_in[20];
    const float* lno_g = (const float*)d_in[21];
    const float* lno_b = (const float*)d_in[22];
    const float* fc1_w = (const float*)d_in[23];
    const float* fc1_b = (const float*)d_in[24];
    const float* fc2_w = (const float*)d_in[25];
    const float* fc2_b = (const float*)d_in[26];
    float* outp = (float*)d_out;

    float *Q, *V0, *V1, *V2, *OFF, *WTS, *ACC, *Y, *Z, *H;
    cudaGetSymbolAddress((void**)&Q,   g_Q);
    cudaGetSymbolAddress((void**)&V0,  g_V0);
    cudaGetSymbolAddress((void**)&V1,  g_V1);
    cudaGetSymbolAddress((void**)&V2,  g_V2);
    cudaGetSymbolAddress((void**)&OFF, g_OFF);
    cudaGetSymbolAddress((void**)&WTS, g_WTS);
    cudaGetSymbolAddress((void**)&ACC, g_ACC);
    cudaGetSymbolAddress((void**)&Y,   g_Y);
    cudaGetSymbolAddress((void**)&Z,   g_Z);
    cudaGetSymbolAddress((void**)&H,   g_H);

    // 1) Q = S_seq @ q_w^T + q_b   (precise path; A m-contiguous)
    gemm_prec(S, (long long)CC * NQ, 1, NQ, q_w, q_b,
              Q, (long long)NQ * CC, CC, NQ, CC, CC, BB);
    ln_kernel<<<BB * NQ, 256>>>(Q, lnq_g, lnq_b);

    // 2) value projections -> position-major [B,P,256]  (fast tf32)
    gemm_fast(f0, (long long)256 * 4096, 1, 4096, vw0, vb0, nullptr, 0, 0, 0,
              V0, (long long)4096 * CC, CC, 1, 4096, CC, 256, 0, BB);
    gemm_fast(f1, (long long)512 * 1024, 1, 1024, vw1, vb1, nullptr, 0, 0, 0,
              V1, (long long)1024 * CC, CC, 1, 1024, CC, 512, 0, BB);
    gemm_fast(f2, (long long)1024 * 256, 1, 256, vw2, vb2, nullptr, 0, 0, 0,
              V2, (long long)256 * CC, CC, 1, 256, CC, 1024, 0, BB);

    // 3) offsets + weights (precise path; A k-contiguous)
    gemm_prec(Q, 0, CC, 1, off_w, off_b, OFF, 0, 96, BB * NQ, 96, CC, 1);
    gemm_prec(Q, 0, CC, 1, wgt_w, wgt_b, WTS, 0, 48, BB * NQ, 48, CC, 1);

    // 4) temperature softmax
    softmax_kernel<<<(BB * NQ * 4 + 255) / 256, 256>>>(WTS, sim);

    // 5) deformable sampling
    sample_kernel<<<BB * NQ * 4, 64>>>(OFF, WTS, V0, V1, V2, ACC);

    // 6) Y = ACC @ out_w^T + out_b
    gemm_fast(ACC, 0, 1024, 1, out_w, out_b, nullptr, 0, 0, 0,
              Y, 0, CC, 1, BB * NQ, CC, 1024, 0, 1);

    // 7) Z = LN(S_seq + Y)
    add_ln_kernel<<<BB * NQ, 256>>>(S, Y, Z, lno_g, lno_b);

    // 8) H = gelu(Z @ fc1_w^T + fc1_b)
    gemm_fast(Z, 0, CC, 1, fc1_w, fc1_b, nullptr, 0, 0, 0,
              H, 0, 1024, 1, BB * NQ, 1024, CC, 1, 1);

    // 9) out = Z + H @ fc2_w^T + fc2_b   (transposed store into [B,C,Hq,Wq])
    gemm_fast(H, (long long)NQ * 1024, 1024, 1, fc2_w, fc2_b,
              Z, (long long)NQ * CC, CC, 1,
              outp, (long long)CC * NQ, 1, NQ, NQ, CC, 1024, 0, BB);
}

// round 4
// speedup vs baseline: 2.9121x; 1.1535x over previous
#include <cuda_runtime.h>
#include <math.h>

#define BB 2
#define CC 256
#define NQ 4096

// ---------------- scratch ----------------
__device__ float g_Q  [BB*NQ*CC];
__device__ float g_V0 [BB*4096*CC];
__device__ float g_V1 [BB*1024*CC];
__device__ float g_V2 [BB*256*CC];
__device__ float g_OFF[BB*NQ*96];
__device__ float g_WTS[BB*NQ*48];
__device__ float g_ACC[(size_t)BB*NQ*1024];
__device__ float g_Y  [BB*NQ*CC];
__device__ float g_Z  [BB*NQ*CC];
__device__ float g_H  [(size_t)BB*NQ*1024];

#define BM 128
#define BN 64

// ---------------- tf32 helpers ----------------
__device__ __forceinline__ float tf32_rna(float x)
{
    unsigned r;
    asm("cvt.rna.tf32.f32 %0, %1;" : "=r"(r) : "f"(x));
    return __uint_as_float(r);
}

__device__ __forceinline__ void mma8(float d[4],
                                     unsigned a0, unsigned a1, unsigned a2, unsigned a3,
                                     unsigned b0, unsigned b1)
{
    asm volatile(
        "mma.sync.aligned.m16n8k8.row.col.f32.tf32.tf32.f32 "
        "{%0,%1,%2,%3},{%4,%5,%6,%7},{%8,%9},{%0,%1,%2,%3};"
        : "+f"(d[0]), "+f"(d[1]), "+f"(d[2]), "+f"(d[3])
        : "r"(a0), "r"(a1), "r"(a2), "r"(a3), "r"(b0), "r"(b1));
}

__device__ __forceinline__ float gelu_exact(float v)
{
    return 0.5f * v * (1.f + erff(v * 0.70710678118654752f));
}

#define U32(x) __float_as_uint(x)

// =====================================================================
// gemm_tc: tf32 tensor-core GEMM.  C[m,n] = sum_k A(m,k)*W[n,k]
// =====================================================================
__global__ void __launch_bounds__(256, 2) gemm_tc(
    const float* __restrict__ A, long long sab, long long sam, long long sak,
    const float* __restrict__ W,
    const float* __restrict__ bias,
    const float* __restrict__ R, long long srb, long long srm, long long srn,
    float* __restrict__ Cout, long long scb, long long scm, long long scn,
    int M, int N, int K, int act)
{
    __shared__ float Ah[2][16][BM + 8];
    __shared__ float Bs[2][16][BN + 8];

    const int tid = threadIdx.x;
    const int lane = tid & 31, warp = tid >> 5;
    const int g = lane >> 2, tg = lane & 3;
    const int wm = (warp >> 2) * 64, wn = (warp & 3) * 16;
    const int m0 = blockIdx.y * BM, n0 = blockIdx.x * BN;
    const bool kc = (sak == 1);

    A    += (long long)blockIdx.z * sab;
    Cout += (long long)blockIdx.z * scb;
    if (R) R += (long long)blockIdx.z * srb;

    float4 rA0, rA1, rW;

#define LOAD(k0)                                                                           \
    if (kc) {                                                                              \
        rA0 = *(const float4*)(A + (long long)(m0 + (tid >> 2)) * sam + ((k0) + (tid & 3) * 4));         \
        rA1 = *(const float4*)(A + (long long)(m0 + 64 + (tid >> 2)) * sam + ((k0) + (tid & 3) * 4));    \
    } else {                                                                               \
        rA0 = *(const float4*)(A + (long long)((k0) + (tid >> 5)) * sak + m0 + (tid & 31) * 4);          \
        rA1 = *(const float4*)(A + (long long)((k0) + 8 + (tid >> 5)) * sak + m0 + (tid & 31) * 4);      \
    }                                                                                      \
    rW = *(const float4*)(W + (long long)(n0 + (tid >> 2)) * K + (k0) + (tid & 3) * 4);

#define STORE(buf)                                                                         \
    if (kc) {                                                                              \
        int k4_ = (tid & 3) * 4, m_ = tid >> 2;                                            \
        Ah[buf][k4_ + 0][m_]      = tf32_rna(rA0.x);                                       \
        Ah[buf][k4_ + 1][m_]      = tf32_rna(rA0.y);                                       \
        Ah[buf][k4_ + 2][m_]      = tf32_rna(rA0.z);                                       \
        Ah[buf][k4_ + 3][m_]      = tf32_rna(rA0.w);                                       \
        Ah[buf][k4_ + 0][m_ + 64] = tf32_rna(rA1.x);                                       \
        Ah[buf][k4_ + 1][m_ + 64] = tf32_rna(rA1.y);                                       \
        Ah[buf][k4_ + 2][m_ + 64] = tf32_rna(rA1.z);                                       \
        Ah[buf][k4_ + 3][m_ + 64] = tf32_rna(rA1.w);                                       \
    } else {                                                                               \
        float4 c0 = make_float4(tf32_rna(rA0.x), tf32_rna(rA0.y), tf32_rna(rA0.z), tf32_rna(rA0.w));     \
        float4 c1 = make_float4(tf32_rna(rA1.x), tf32_rna(rA1.y), tf32_rna(rA1.z), tf32_rna(rA1.w));     \
        *(float4*)&Ah[buf][tid >> 5][(tid & 31) * 4]       = c0;                           \
        *(float4*)&Ah[buf][8 + (tid >> 5)][(tid & 31) * 4] = c1;                           \
    }                                                                                      \
    {   int n_ = tid >> 2, k4_ = (tid & 3) * 4;                                            \
        Bs[buf][k4_ + 0][n_] = tf32_rna(rW.x);                                             \
        Bs[buf][k4_ + 1][n_] = tf32_rna(rW.y);                                             \
        Bs[buf][k4_ + 2][n_] = tf32_rna(rW.z);                                             \
        Bs[buf][k4_ + 3][n_] = tf32_rna(rW.w); }

    LOAD(0); STORE(0);
    __syncthreads();

    float acc[4][2][4] = {};
    const int nk = K / 16;

    for (int t = 0; t < nk; t++) {
        const int buf = t & 1;
        const bool more = (t + 1 < nk);
        if (more) { LOAD((t + 1) * 16); }

        // hoist B fragments for both k-slabs (8 regs)
        unsigned bF[2][2][2];
        #pragma unroll
        for (int s = 0; s < 2; s++) {
            #pragma unroll
            for (int nt = 0; nt < 2; nt++) {
                bF[s][nt][0] = U32(Bs[buf][s * 8 + tg][wn + 8 * nt + g]);
                bF[s][nt][1] = U32(Bs[buf][s * 8 + tg + 4][wn + 8 * nt + g]);
            }
        }
        // per m-tile: load both slabs' A fragments, then 4 MMAs
        #pragma unroll
        for (int mt = 0; mt < 4; mt++) {
            unsigned aF[2][4];
            #pragma unroll
            for (int s = 0; s < 2; s++) {
                aF[s][0] = U32(Ah[buf][s * 8 + tg][wm + 16 * mt + g]);
                aF[s][1] = U32(Ah[buf][s * 8 + tg][wm + 16 * mt + g + 8]);
                aF[s][2] = U32(Ah[buf][s * 8 + tg + 4][wm + 16 * mt + g]);
                aF[s][3] = U32(Ah[buf][s * 8 + tg + 4][wm + 16 * mt + g + 8]);
            }
            #pragma unroll
            for (int s = 0; s < 2; s++)
                #pragma unroll
                for (int nt = 0; nt < 2; nt++)
                    mma8(acc[mt][nt], aF[s][0], aF[s][1], aF[s][2], aF[s][3],
                         bF[s][nt][0], bF[s][nt][1]);
        }
        if (more) { STORE(buf ^ 1); }
        __syncthreads();
    }
#undef LOAD
#undef STORE

    // epilogue
    #pragma unroll
    for (int mt = 0; mt < 4; mt++) {
        int gm0 = m0 + wm + 16 * mt + g;
        #pragma unroll
        for (int nt = 0; nt < 2; nt++) {
            int gn0 = n0 + wn + 8 * nt + 2 * tg;
            float v0 = acc[mt][nt][0], v1 = acc[mt][nt][1];
            float v2 = acc[mt][nt][2], v3 = acc[mt][nt][3];
            if (bias) {
                float b0 = bias[gn0], b1 = bias[gn0 + 1];
                v0 += b0; v1 += b1; v2 += b0; v3 += b1;
            }
            if (act) {
                v0 = gelu_exact(v0); v1 = gelu_exact(v1);
                v2 = gelu_exact(v2); v3 = gelu_exact(v3);
            }
            if (R) {
                v0 += R[(long long)gm0 * srm + (long long)gn0 * srn];
                v1 += R[(long long)gm0 * srm + (long long)(gn0 + 1) * srn];
                v2 += R[(long long)(gm0 + 8) * srm + (long long)gn0 * srn];
                v3 += R[(long long)(gm0 + 8) * srm + (long long)(gn0 + 1) * srn];
            }
            if (scn == 1) {
                *(float2*)(Cout + (long long)gm0 * scm + gn0)       = make_float2(v0, v1);
                *(float2*)(Cout + (long long)(gm0 + 8) * scm + gn0) = make_float2(v2, v3);
            } else {
                Cout[(long long)gm0 * scm + (long long)gn0 * scn]             = v0;
                Cout[(long long)gm0 * scm + (long long)(gn0 + 1) * scn]       = v1;
                Cout[(long long)(gm0 + 8) * scm + (long long)gn0 * scn]       = v2;
                Cout[(long long)(gm0 + 8) * scm + (long long)(gn0 + 1) * scn] = v3;
            }
        }
    }
}

// =====================================================================
// gemm_tc3: 3xTF32 (fp32-accurate) GEMM for the offset-sensitive path.
// =====================================================================
__global__ void __launch_bounds__(256, 2) gemm_tc3(
    const float* __restrict__ A, long long sab, long long sam, long long sak,
    const float* __restrict__ W,
    const float* __restrict__ bias,
    float* __restrict__ Cout, long long scb, long long scm,
    int M, int N, int K)
{
    __shared__ float Ah[2][8][BM + 8];
    __shared__ float Al[2][8][BM + 8];
    __shared__ float Bh[2][8][BN + 8];
    __shared__ float Bl[2][8][BN + 8];

    const int tid = threadIdx.x;
    const int lane = tid & 31, warp = tid >> 5;
    const int g = lane >> 2, tg = lane & 3;
    const int wm = (warp >> 2) * 64, wn = (warp & 3) * 16;
    const int m0 = blockIdx.y * BM, n0 = blockIdx.x * BN;
    const bool kc = (sak == 1);

    A    += (long long)blockIdx.z * sab;
    Cout += (long long)blockIdx.z * scb;

    float4 rA, rW;

#define LOAD3(k0)                                                                          \
    if (kc) {                                                                              \
        rA = *(const float4*)(A + (long long)(m0 + (tid >> 1)) * sam + ((k0) + (tid & 1) * 4));          \
    } else {                                                                               \
        rA = *(const float4*)(A + (long long)((k0) + (tid >> 5)) * sak + m0 + (tid & 31) * 4);           \
    }                                                                                      \
    if (tid < 128) {                                                                       \
        int gn_ = n0 + (tid >> 1);                                                         \
        rW = (gn_ < N) ? *(const float4*)(W + (long long)gn_ * K + (k0) + (tid & 1) * 4)   \
                       : make_float4(0.f, 0.f, 0.f, 0.f);                                  \
    }

#define SPLIT(x, hi, lo) { hi = tf32_rna(x); lo = tf32_rna((x) - hi); }

#define STORE3(buf)                                                                        \
    {   float h_, l_;                                                                      \
        if (kc) {                                                                          \
            int k4_ = (tid & 1) * 4, m_ = tid >> 1;                                        \
            SPLIT(rA.x, h_, l_); Ah[buf][k4_ + 0][m_] = h_; Al[buf][k4_ + 0][m_] = l_;     \
            SPLIT(rA.y, h_, l_); Ah[buf][k4_ + 1][m_] = h_; Al[buf][k4_ + 1][m_] = l_;     \
            SPLIT(rA.z, h_, l_); Ah[buf][k4_ + 2][m_] = h_; Al[buf][k4_ + 2][m_] = l_;     \
            SPLIT(rA.w, h_, l_); Ah[buf][k4_ + 3][m_] = h_; Al[buf][k4_ + 3][m_] = l_;     \
        } else {                                                                           \
            int row_ = tid >> 5, col_ = (tid & 31) * 4;                                    \
            SPLIT(rA.x, h_, l_); Ah[buf][row_][col_ + 0] = h_; Al[buf][row_][col_ + 0] = l_;  \
            SPLIT(rA.y, h_, l_); Ah[buf][row_][col_ + 1] = h_; Al[buf][row_][col_ + 1] = l_;  \
            SPLIT(rA.z, h_, l_); Ah[buf][row_][col_ + 2] = h_; Al[buf][row_][col_ + 2] = l_;  \
            SPLIT(rA.w, h_, l_); Ah[buf][row_][col_ + 3] = h_; Al[buf][row_][col_ + 3] = l_;  \
        }                                                                                  \
        if (tid < 128) {                                                                   \
            int n_ = tid >> 1, k4_ = (tid & 1) * 4;                                        \
            SPLIT(rW.x, h_, l_); Bh[buf][k4_ + 0][n_] = h_; Bl[buf][k4_ + 0][n_] = l_;     \
            SPLIT(rW.y, h_, l_); Bh[buf][k4_ + 1][n_] = h_; Bl[buf][k4_ + 1][n_] = l_;     \
            SPLIT(rW.z, h_, l_); Bh[buf][k4_ + 2][n_] = h_; Bl[buf][k4_ + 2][n_] = l_;     \
            SPLIT(rW.w, h_, l_); Bh[buf][k4_ + 3][n_] = h_; Bl[buf][k4_ + 3][n_] = l_;     \
        }                                                                                  \
    }

    LOAD3(0); STORE3(0);
    __syncthreads();

    float acc[4][2][4] = {};
    const int nk = K / 8;

    for (int t = 0; t < nk; t++) {
        const int buf = t & 1;
        const bool more = (t + 1 < nk);
        if (more) { LOAD3((t + 1) * 8); }

        unsigned bh[2][2], bl[2][2];
        #pragma unroll
        for (int nt = 0; nt < 2; nt++) {
            bh[nt][0] = U32(Bh[buf][tg][wn + 8 * nt + g]);
            bh[nt][1] = U32(Bh[buf][tg + 4][wn + 8 * nt + g]);
            bl[nt][0] = U32(Bl[buf][tg][wn + 8 * nt + g]);
            bl[nt][1] = U32(Bl[buf][tg + 4][wn + 8 * nt + g]);
        }
        #pragma unroll
        for (int mt = 0; mt < 4; mt++) {
            unsigned a0 = U32(Ah[buf][tg][wm + 16 * mt + g]);
            unsigned a1 = U32(Ah[buf][tg][wm + 16 * mt + g + 8]);
            unsigned a2 = U32(Ah[buf][tg + 4][wm + 16 * mt + g]);
            unsigned a3 = U32(Ah[buf][tg + 4][wm + 16 * mt + g + 8]);
            unsigned l0 = U32(Al[buf][tg][wm + 16 * mt + g]);
            unsigned l1 = U32(Al[buf][tg][wm + 16 * mt + g + 8]);
            unsigned l2 = U32(Al[buf][tg + 4][wm + 16 * mt + g]);
            unsigned l3 = U32(Al[buf][tg + 4][wm + 16 * mt + g + 8]);
            #pragma unroll
            for (int nt = 0; nt < 2; nt++) {
                mma8(acc[mt][nt], l0, l1, l2, l3, bh[nt][0], bh[nt][1]);
                mma8(acc[mt][nt], a0, a1, a2, a3, bl[nt][0], bl[nt][1]);
                mma8(acc[mt][nt], a0, a1, a2, a3, bh[nt][0], bh[nt][1]);
            }
        }
        if (more) { STORE3(buf ^ 1); }
        __syncthreads();
    }
#undef LOAD3
#undef STORE3
#undef SPLIT

    #pragma unroll
    for (int mt = 0; mt < 4; mt++) {
        int gm0 = m0 + wm + 16 * mt + g;
        #pragma unroll
        for (int nt = 0; nt < 2; nt++) {
            int gn0 = n0 + wn + 8 * nt + 2 * tg;
            if (gn0 >= N) continue;
            float v0 = acc[mt][nt][0], v1 = acc[mt][nt][1];
            float v2 = acc[mt][nt][2], v3 = acc[mt][nt][3];
            if (bias) {
                float b0 = bias[gn0], b1 = bias[gn0 + 1];
                v0 += b0; v1 += b1; v2 += b0; v3 += b1;
            }
            *(float2*)(Cout + (long long)gm0 * scm + gn0)       = make_float2(v0, v1);
            *(float2*)(Cout + (long long)(gm0 + 8) * scm + gn0) = make_float2(v2, v3);
        }
    }
}

// ---------------- block reduction ----------------
__device__ __forceinline__ float block_sum256(float v)
{
    __shared__ float red[8];
    #pragma unroll
    for (int o = 16; o; o >>= 1) v += __shfl_xor_sync(0xffffffffu, v, o);
    __syncthreads();
    if ((threadIdx.x & 31) == 0) red[threadIdx.x >> 5] = v;
    __syncthreads();
    float s = red[0];
    #pragma unroll
    for (int i = 1; i < 8; i++) s += red[i];
    return s;
}

__global__ void ln_kernel(float* __restrict__ X,
                          const float* __restrict__ g, const float* __restrict__ b)
{
    long long row = blockIdx.x;
    int c = threadIdx.x;
    float v = X[row * CC + c];
    float mu = block_sum256(v) * (1.f / CC);
    float d = v - mu;
    __syncthreads();
    float var = block_sum256(d * d) * (1.f / CC);
    float r = rsqrtf(var + 1e-5f);
    X[row * CC + c] = d * r * g[c] + b[c];
}

__global__ void add_ln_kernel(const float* __restrict__ S, const float* __restrict__ Y,
                              float* __restrict__ Z,
                              const float* __restrict__ g, const float* __restrict__ b_)
{
    long long row = blockIdx.x;
    int c = threadIdx.x;
    int bb = (int)(row / NQ), nq = (int)(row % NQ);
    float v = S[((long long)bb * CC + c) * NQ + nq] + Y[row * CC + c];
    float mu = block_sum256(v) * (1.f / CC);
    float d = v - mu;
    __syncthreads();
    float var = block_sum256(d * d) * (1.f / CC);
    float r = rsqrtf(var + 1e-5f);
    Z[row * CC + c] = d * r * g[c] + b_[c];
}

// ---------------- fused softmax + deformable sampling ----------------
// one block per (b,nq), 256 threads = 4 heads x 64 channel-quads
__global__ void sample_kernel(const float* __restrict__ OFF, const float* __restrict__ WTS,
                              const float* __restrict__ sim,
                              const float* __restrict__ V0, const float* __restrict__ V1,
                              const float* __restrict__ V2, float* __restrict__ ACC)
{
    int q = blockIdx.x;             // b*NQ + nq
    int bb = q / NQ, nq = q % NQ;
    int hq = nq >> 6, wq = nq & 63;

    __shared__ float sx[48], sy[48], sw[48];
    int t = threadIdx.x;
    if (t < 48) {
        float refx = (wq + 0.5f) * (1.f / 64.f);
        float refy = (hq + 0.5f) * (1.f / 64.f);
        const float* off = OFF + (long long)q * 96 + t * 2;
        sx[t] = tanhf(2.f * (refx + off[0]) - 1.f);
        sy[t] = tanhf(2.f * (refy + off[1]) - 1.f);
        sw[t] = WTS[(long long)q * 48 + t] * (sim[q] + 0.001f);
    }
    __syncthreads();
    if (t < 4) {
        float* w = sw + t * 12;
        float mx = -1e30f;
        #pragma unroll
        for (int p = 0; p < 12; p++) mx = fmaxf(mx, w[p]);
        float sum = 0.f;
        #pragma unroll
        for (int p = 0; p < 12; p++) { w[p] = expf(w[p] - mx); sum += w[p]; }
        float inv = 1.f / sum;
        #pragma unroll
        for (int p = 0; p < 12; p++) w[p] *= inv;
    }
    __syncthreads();

    int h = t >> 6;
    int c4 = (t & 63) * 4;
    float4 acc = make_float4(0.f, 0.f, 0.f, 0.f);

    #pragma unroll
    for (int l = 0; l < 3; l++) {
        int sz = 64 >> l;
        const float* Vb = (l == 0) ? V0 + (long long)bb * 4096 * CC
                        : (l == 1) ? V1 + (long long)bb * 1024 * CC
                                   : V2 + (long long)bb * 256 * CC;
        #pragma unroll
        for (int m = 0; m < 4; m++) {
            int p = h * 12 + l * 4 + m;
            float x = (sx[p] + 1.f) * 0.5f * (sz - 1);
            float y = (sy[p] + 1.f) * 0.5f * (sz - 1);
            float x0f = floorf(x), y0f = floorf(y);
            int x0 = (int)x0f, y0 = (int)y0f;
            float wx1 = x - x0f, wy1 = y - y0f;
            float wx0 = 1.f - wx1, wy0 = 1.f - wy1;
            float w = sw[p];
            #pragma unroll
            for (int dy = 0; dy < 2; dy++) {
                int yi = y0 + dy;
                if (yi < 0 || yi >= sz) continue;
                float wyv = dy ? wy1 : wy0;
                #pragma unroll
                for (int dx = 0; dx < 2; dx++) {
                    int xi = x0 + dx;
                    if (xi < 0 || xi >= sz) continue;
                    float tw = w * wyv * (dx ? wx1 : wx0);
                    const float4 v = __ldg((const float4*)(Vb + ((long long)(yi * sz + xi)) * CC + c4));
                    acc.x += tw * v.x; acc.y += tw * v.y;
                    acc.z += tw * v.z; acc.w += tw * v.w;
                }
            }
        }
    }
    float* out = ACC + (long long)q * 1024 + h * CC + c4;
    *(float4*)out = acc;
}

// ---------------- host orchestration ----------------
struct Streams {
    cudaStream_t s1, s2, s3;
    cudaEvent_t evRoot, ev1, ev2, evA, evW;
    Streams() {
        cudaStreamCreateWithFlags(&s1, cudaStreamNonBlocking);
        cudaStreamCreateWithFlags(&s2, cudaStreamNonBlocking);
        cudaStreamCreateWithFlags(&s3, cudaStreamNonBlocking);
        cudaEventCreateWithFlags(&evRoot, cudaEventDisableTiming);
        cudaEventCreateWithFlags(&ev1, cudaEventDisableTiming);
        cudaEventCreateWithFlags(&ev2, cudaEventDisableTiming);
        cudaEventCreateWithFlags(&evA, cudaEventDisableTiming);
        cudaEventCreateWithFlags(&evW, cudaEventDisableTiming);
    }
};

static void gemm_fast(cudaStream_t st,
                      const float* A, long long sab, long long sam, long long sak,
                      const float* W, const float* bias,
                      const float* R, long long srb, long long srm, long long srn,
                      float* C, long long scb, long long scm, long long scn,
                      int M, int N, int K, int act, int batch)
{
    dim3 grid(N / BN, M / BM, batch);
    gemm_tc<<<grid, 256, 0, st>>>(A, sab, sam, sak, W, bias, R, srb, srm, srn,
                                  C, scb, scm, scn, M, N, K, act);
}

static void gemm_prec(cudaStream_t st,
                      const float* A, long long sab, long long sam, long long sak,
                      const float* W, const float* bias,
                      float* C, long long scb, long long scm,
                      int M, int N, int K, int batch)
{
    dim3 grid((N + BN - 1) / BN, M / BM, batch);
    gemm_tc3<<<grid, 256, 0, st>>>(A, sab, sam, sak, W, bias, C, scb, scm, M, N, K);
}

extern "C" void kernel_launch(void* const* d_in, const int* in_sizes, int n_in,
                              void* d_out, int out_size)
{
    static Streams str;   // created once on first (non-captured) call

    const float* S     = (const float*)d_in[0];
    const float* f0    = (const float*)d_in[1];
    const float* f1    = (const float*)d_in[2];
    const float* f2    = (const float*)d_in[3];
    const float* sim   = (const float*)d_in[4];
    const float* vw0   = (const float*)d_in[5];
    const float* vb0   = (const float*)d_in[6];
    const float* vw1   = (const float*)d_in[7];
    const float* vb1   = (const float*)d_in[8];
    const float* vw2   = (const float*)d_in[9];
    const float* vb2   = (const float*)d_in[10];
    const float* q_w   = (const float*)d_in[11];
    const float* q_b   = (const float*)d_in[12];
    const float* off_w = (const float*)d_in[13];
    const float* off_b = (const float*)d_in[14];
    const float* wgt_w = (const float*)d_in[15];
    const float* wgt_b = (const float*)d_in[16];
    const float* out_w = (const float*)d_in[17];
    const float* out_b = (const float*)d_in[18];
    const float* lnq_g = (const float*)d_in[19];
    const float* lnq_b = (const float*)d_in[20];
    const float* lno_g = (const float*)d_in[21];
    const float* lno_b = (const float*)d_in[22];
    const float* fc1_w = (const float*)d_in[23];
    const float* fc1_b = (const float*)d_in[24];
    const float* fc2_w = (const float*)d_in[25];
    const float* fc2_b = (const float*)d_in[26];
    float* outp = (float*)d_out;

    float *Q, *V0, *V1, *V2, *OFF, *WTS, *ACC, *Y, *Z, *H;
    cudaGetSymbolAddress((void**)&Q,   g_Q);
    cudaGetSymbolAddress((void**)&V0,  g_V0);
    cudaGetSymbolAddress((void**)&V1,  g_V1);
    cudaGetSymbolAddress((void**)&V2,  g_V2);
    cudaGetSymbolAddress((void**)&OFF, g_OFF);
    cudaGetSymbolAddress((void**)&WTS, g_WTS);
    cudaGetSymbolAddress((void**)&ACC, g_ACC);
    cudaGetSymbolAddress((void**)&Y,   g_Y);
    cudaGetSymbolAddress((void**)&Z,   g_Z);
    cudaGetSymbolAddress((void**)&H,   g_H);

    cudaStream_t s0 = 0;

    // ---- fork: V projections on s1/s2/s3, concurrent with the Q chain ----
    cudaEventRecord(str.evRoot, s0);
    cudaStreamWaitEvent(str.s1, str.evRoot, 0);
    cudaStreamWaitEvent(str.s2, str.evRoot, 0);
    cudaStreamWaitEvent(str.s3, str.evRoot, 0);

    gemm_fast(str.s1, f0, (long long)256 * 4096, 1, 4096, vw0, vb0, nullptr, 0, 0, 0,
              V0, (long long)4096 * CC, CC, 1, 4096, CC, 256, 0, BB);
    gemm_fast(str.s2, f1, (long long)512 * 1024, 1, 1024, vw1, vb1, nullptr, 0, 0, 0,
              V1, (long long)1024 * CC, CC, 1, 1024, CC, 512, 0, BB);
    gemm_fast(str.s3, f2, (long long)1024 * 256, 1, 256, vw2, vb2, nullptr, 0, 0, 0,
              V2, (long long)256 * CC, CC, 1, 256, CC, 1024, 0, BB);
    cudaEventRecord(str.ev1, str.s1);
    cudaEventRecord(str.ev2, str.s2);

    // ---- main chain on s0 ----
    gemm_prec(s0, S, (long long)CC * NQ, 1, NQ, q_w, q_b,
              Q, (long long)NQ * CC, CC, NQ, CC, CC, BB);
    ln_kernel<<<BB * NQ, 256, 0, s0>>>(Q, lnq_g, lnq_b);

    // fork: wgt on s3 (after its V2 work) in parallel with off on s0
    cudaEventRecord(str.evA, s0);
    cudaStreamWaitEvent(str.s3, str.evA, 0);
    gemm_prec(str.s3, Q, 0, CC, 1, wgt_w, wgt_b, WTS, 0, 48, BB * NQ, 48, CC, 1);
    cudaEventRecord(str.evW, str.s3);

    gemm_prec(s0, Q, 0, CC, 1, off_w, off_b, OFF, 0, 96, BB * NQ, 96, CC, 1);

    // join: need WTS, V0, V1, V2 (V2 ordered before evW on s3)
    cudaStreamWaitEvent(s0, str.evW, 0);
    cudaStreamWaitEvent(s0, str.ev1, 0);
    cudaStreamWaitEvent(s0, str.ev2, 0);

    // fused softmax + sampling
    sample_kernel<<<BB * NQ, 256, 0, s0>>>(OFF, WTS, sim, V0, V1, V2, ACC);

    // out projection
    gemm_fast(s0, ACC, 0, 1024, 1, out_w, out_b, nullptr, 0, 0, 0,
              Y, 0, CC, 1, BB * NQ, CC, 1024, 0, 1);

    add_ln_kernel<<<BB * NQ, 256, 0, s0>>>(S, Y, Z, lno_g, lno_b);

    gemm_fast(s0, Z, 0, CC, 1, fc1_w, fc1_b, nullptr, 0, 0, 0,
              H, 0, 1024, 1, BB * NQ, 1024, CC, 1, 1);

    gemm_fast(s0, H, (long long)NQ * 1024, 1024, 1, fc2_w, fc2_b,
              Z, (long long)NQ * CC, CC, 1,
              outp, (long long)CC * NQ, 1, NQ, NQ, CC, 1024, 0, BB);
}